// round 2
// baseline (speedup 1.0000x reference)
#include <cuda_runtime.h>
#include <cuda_bf16.h>
#include <cstdint>

// Problem constants
#define NB 8
#define SEQ 1024
#define EMB 1024
#define NH 16
#define DK 64
#define MROWS (NB * SEQ)   // 8192

// Scratch buffers (device globals: allocation-free rule)
__device__ float g_Q[(size_t)NB * SEQ * EMB];
__device__ float g_K[(size_t)NB * SEQ * EMB];
__device__ float g_V[(size_t)NB * SEQ * EMB];
__device__ float g_O[(size_t)NB * SEQ * EMB];

// ============================================================================
// SGEMM with bias: C[M,N] = A[M,K] @ B[K,N] + bias[N]
// BM=128, BN=128, BK=16, 256 threads, 8x8 per thread
// ============================================================================
__global__ __launch_bounds__(256) void sgemm_bias_kernel(
    const float* __restrict__ A, const float* __restrict__ B,
    const float* __restrict__ bias, float* __restrict__ C,
    int M, int N, int K)
{
    __shared__ float As[16][128];   // transposed A tile: As[k][m]
    __shared__ float Bs[16][128];   // Bs[k][n]

    const int tid = threadIdx.x;
    const int brow = blockIdx.y * 128;
    const int bcol = blockIdx.x * 128;
    const int ty = tid >> 4;        // 0..15 -> row group
    const int tx = tid & 15;        // 0..15 -> col group

    float acc[8][8];
#pragma unroll
    for (int i = 0; i < 8; i++)
#pragma unroll
        for (int j = 0; j < 8; j++) acc[i][j] = 0.f;

    for (int k0 = 0; k0 < K; k0 += 16) {
        // Load A tile: 128 rows x 16 cols = 512 float4; 2 per thread
#pragma unroll
        for (int i = 0; i < 2; i++) {
            int idx = tid + i * 256;          // 0..511
            int r = idx >> 2;                 // row 0..127
            int c4 = (idx & 3) << 2;          // col 0,4,8,12
            float4 a = *(const float4*)&A[(size_t)(brow + r) * K + k0 + c4];
            As[c4 + 0][r] = a.x;
            As[c4 + 1][r] = a.y;
            As[c4 + 2][r] = a.z;
            As[c4 + 3][r] = a.w;
        }
        // Load B tile: 16 rows x 128 cols = 512 float4; 2 per thread
#pragma unroll
        for (int i = 0; i < 2; i++) {
            int idx = tid + i * 256;
            int r = idx >> 5;                 // row 0..15
            int c = (idx & 31) << 2;          // col 0..124
            *(float4*)&Bs[r][c] = *(const float4*)&B[(size_t)(k0 + r) * N + bcol + c];
        }
        __syncthreads();

#pragma unroll
        for (int kk = 0; kk < 16; kk++) {
            float ra[8], rb[8];
            *(float4*)&ra[0] = *(const float4*)&As[kk][ty * 8];
            *(float4*)&ra[4] = *(const float4*)&As[kk][ty * 8 + 4];
            *(float4*)&rb[0] = *(const float4*)&Bs[kk][tx * 8];
            *(float4*)&rb[4] = *(const float4*)&Bs[kk][tx * 8 + 4];
#pragma unroll
            for (int i = 0; i < 8; i++)
#pragma unroll
                for (int j = 0; j < 8; j++)
                    acc[i][j] += ra[i] * rb[j];
        }
        __syncthreads();
    }

    // Epilogue: add bias, store
#pragma unroll
    for (int i = 0; i < 8; i++) {
        int r = brow + ty * 8 + i;
#pragma unroll
        for (int j = 0; j < 8; j += 4) {
            int c = bcol + tx * 8 + j;
            float4 bb = *(const float4*)&bias[c];
            float4 v;
            v.x = acc[i][j + 0] + bb.x;
            v.y = acc[i][j + 1] + bb.y;
            v.z = acc[i][j + 2] + bb.z;
            v.w = acc[i][j + 3] + bb.w;
            *(float4*)&C[(size_t)r * N + c] = v;
        }
    }
}

// ============================================================================
// Flash-style attention: one thread per query row; 128 q-rows per block.
// q[64], o[64], s[64] in registers; K/V tiles (64x64) in shared memory.
// Mask is int32 (0 = keep, nonzero = suppress with -1e9).
// grid: (SEQ/128, NH, NB), block: 128 threads
// ============================================================================
__global__ __launch_bounds__(128) void attn_kernel(
    const float* __restrict__ Q, const float* __restrict__ K,
    const float* __restrict__ V, const int* __restrict__ mask,
    float* __restrict__ O)
{
    __shared__ float kS[64][64];
    __shared__ float vS[64][64];

    const int t = threadIdx.x;
    const int n = blockIdx.z;
    const int h = blockIdx.y;
    const int qrow = blockIdx.x * 128 + t;
    const size_t headoff = (size_t)h * DK;

    const float* Qp = Q + ((size_t)n * SEQ + qrow) * EMB + headoff;
    float q[DK];
#pragma unroll
    for (int d = 0; d < DK; d++) q[d] = Qp[d] * 0.125f;   // fold 1/sqrt(64)

    float o[DK];
#pragma unroll
    for (int d = 0; d < DK; d++) o[d] = 0.f;
    float m = -1e30f, l = 0.f;

    const int* mrow = mask + ((size_t)n * SEQ + qrow) * SEQ;
    const float* Kbase = K + ((size_t)n * SEQ) * EMB + headoff;
    const float* Vbase = V + ((size_t)n * SEQ) * EMB + headoff;

    for (int j = 0; j < SEQ / 64; j++) {
        const int kb = j * 64;
        __syncthreads();   // protect previous tile reads
        // Cooperative load: 64x64 floats each = 1024 float4; 8 per thread
#pragma unroll
        for (int i = 0; i < 8; i++) {
            int idx = t + i * 128;
            int r = idx >> 4;
            int c = (idx & 15) << 2;
            *(float4*)&kS[r][c] = *(const float4*)&Kbase[(size_t)(kb + r) * EMB + c];
            *(float4*)&vS[r][c] = *(const float4*)&Vbase[(size_t)(kb + r) * EMB + c];
        }
        __syncthreads();

        // S = q . K^T (scaled already)
        float s[64];
#pragma unroll
        for (int k = 0; k < 64; k++) {
            float acc = 0.f;
#pragma unroll
            for (int d = 0; d < DK; d++) acc += q[d] * kS[k][d];
            s[k] = acc;
        }

        // Apply mask (int32): nonzero -> -1e9 (matches reference masked_fill)
#pragma unroll
        for (int k = 0; k < 64; k += 4) {
            int4 mv = *(const int4*)&mrow[kb + k];
            if (mv.x) s[k + 0] = -1e9f;
            if (mv.y) s[k + 1] = -1e9f;
            if (mv.z) s[k + 2] = -1e9f;
            if (mv.w) s[k + 3] = -1e9f;
        }

        // Online softmax
        float tmax = s[0];
#pragma unroll
        for (int k = 1; k < 64; k++) tmax = fmaxf(tmax, s[k]);
        float m_new = fmaxf(m, tmax);
        float c = __expf(m - m_new);
        l *= c;
        float sum = 0.f;
#pragma unroll
        for (int k = 0; k < 64; k++) {
            float p = __expf(s[k] - m_new);
            s[k] = p;
            sum += p;
        }
        l += sum;
#pragma unroll
        for (int d = 0; d < DK; d++) o[d] *= c;

        // O += P @ V
#pragma unroll
        for (int d = 0; d < DK; d++) {
            float acc = o[d];
#pragma unroll
            for (int k = 0; k < 64; k++) acc += s[k] * vS[k][d];
            o[d] = acc;
        }
        m = m_new;
    }

    const float inv = 1.f / l;
    float* Op = O + ((size_t)n * SEQ + qrow) * EMB + headoff;
#pragma unroll
    for (int d = 0; d < DK; d += 4) {
        float4 v;
        v.x = o[d + 0] * inv;
        v.y = o[d + 1] * inv;
        v.z = o[d + 2] * inv;
        v.w = o[d + 3] * inv;
        *(float4*)&Op[d] = v;
    }
}

// ============================================================================
// Launch
// ============================================================================
extern "C" void kernel_launch(void* const* d_in, const int* in_sizes, int n_in,
                              void* d_out, int out_size)
{
    const float* x  = (const float*)d_in[0];
    const int* mask = (const int*)d_in[1];
    const float* Wq = (const float*)d_in[2];
    const float* bq = (const float*)d_in[3];
    const float* Wk = (const float*)d_in[4];
    const float* bk = (const float*)d_in[5];
    const float* Wv = (const float*)d_in[6];
    const float* bv = (const float*)d_in[7];
    const float* Wo = (const float*)d_in[8];
    const float* bo = (const float*)d_in[9];
    float* out = (float*)d_out;

    float *Qp, *Kp, *Vp, *Op;
    cudaGetSymbolAddress((void**)&Qp, g_Q);
    cudaGetSymbolAddress((void**)&Kp, g_K);
    cudaGetSymbolAddress((void**)&Vp, g_V);
    cudaGetSymbolAddress((void**)&Op, g_O);

    dim3 ggrid(EMB / 128, MROWS / 128);   // (8, 64)
    sgemm_bias_kernel<<<ggrid, 256>>>(x, Wq, bq, Qp, MROWS, EMB, EMB);
    sgemm_bias_kernel<<<ggrid, 256>>>(x, Wk, bk, Kp, MROWS, EMB, EMB);
    sgemm_bias_kernel<<<ggrid, 256>>>(x, Wv, bv, Vp, MROWS, EMB, EMB);

    dim3 agrid(SEQ / 128, NH, NB);        // (8, 16, 8)
    attn_kernel<<<agrid, 128>>>(Qp, Kp, Vp, mask, Op);

    sgemm_bias_kernel<<<ggrid, 256>>>(Op, Wo, bo, out, MROWS, EMB, EMB);
}

// round 3
// speedup vs baseline: 1.2928x; 1.2928x over previous
#include <cuda_runtime.h>
#include <cuda_bf16.h>
#include <cstdint>

// Problem constants
#define NB 8
#define SEQ 1024
#define EMB 1024
#define NH 16
#define DK 64
#define MROWS (NB * SEQ)   // 8192

// Scratch buffers (device globals: allocation-free rule)
__device__ float g_Q[(size_t)NB * SEQ * EMB];
__device__ float g_K[(size_t)NB * SEQ * EMB];
__device__ float g_V[(size_t)NB * SEQ * EMB];
__device__ float g_O[(size_t)NB * SEQ * EMB];

// ============================================================================
// Tensor-core GEMM (split-bf16, 3 MMAs per product => ~fp32 accuracy)
// C[M,N] = A[M,K] @ B[K,N] + bias[N];  M=8192, N=K=1024
// Block tile 128x128x32, 256 threads (8 warps, 2x4), warp tile 64x32.
// ============================================================================
#define BM 128
#define BN 128
#define BKK 32
#define NIT (EMB / BKK)          // 32 k-iterations
#define ASTR 40                  // A smem row stride (bf16 elems), conflict-free + 16B aligned
#define BSTR 136                 // B smem row stride
#define A_ELEMS (BM * ASTR)      // 5120
#define B_ELEMS (BKK * BSTR)     // 4352
#define OFF_AH 0
#define OFF_AL (A_ELEMS)
#define OFF_BH (2 * A_ELEMS)
#define OFF_BL (2 * A_ELEMS + B_ELEMS)
#define STAGE_ELEMS (2 * A_ELEMS + 2 * B_ELEMS)   // 18944 bf16
#define GEMM_SMEM_BYTES (2 * STAGE_ELEMS * 2)     // 75776 bytes (double-buffered)

__device__ __forceinline__ void ldsm4(uint32_t& r0, uint32_t& r1, uint32_t& r2, uint32_t& r3, uint32_t a) {
    asm volatile("ldmatrix.sync.aligned.m8n8.x4.shared.b16 {%0,%1,%2,%3}, [%4];"
                 : "=r"(r0), "=r"(r1), "=r"(r2), "=r"(r3) : "r"(a));
}
__device__ __forceinline__ void ldsm4t(uint32_t& r0, uint32_t& r1, uint32_t& r2, uint32_t& r3, uint32_t a) {
    asm volatile("ldmatrix.sync.aligned.m8n8.x4.trans.shared.b16 {%0,%1,%2,%3}, [%4];"
                 : "=r"(r0), "=r"(r1), "=r"(r2), "=r"(r3) : "r"(a));
}
__device__ __forceinline__ void mma_bf16(float* c, const uint32_t* a, const uint32_t* b) {
    asm volatile("mma.sync.aligned.m16n8k16.row.col.f32.bf16.bf16.f32 "
                 "{%0,%1,%2,%3}, {%4,%5,%6,%7}, {%8,%9}, {%0,%1,%2,%3};"
                 : "+f"(c[0]), "+f"(c[1]), "+f"(c[2]), "+f"(c[3])
                 : "r"(a[0]), "r"(a[1]), "r"(a[2]), "r"(a[3]), "r"(b[0]), "r"(b[1]));
}
__device__ __forceinline__ uint32_t pack_bf16(__nv_bfloat16 e, __nv_bfloat16 o) {
    __nv_bfloat162 p(e, o);          // .x = even k (low 16 bits), .y = odd k
    return *(uint32_t*)&p;
}
__device__ __forceinline__ void split1(float v, __nv_bfloat16& h, __nv_bfloat16& l) {
    h = __float2bfloat16(v);
    l = __float2bfloat16(v - __bfloat162float(h));
}

__global__ __launch_bounds__(256, 1) void gemm_bf16x3_kernel(
    const float* __restrict__ A, const float* __restrict__ B,
    const float* __restrict__ bias, float* __restrict__ C)
{
    extern __shared__ __align__(16) __nv_bfloat16 sm[];
    const int tid = threadIdx.x;
    const int lane = tid & 31, warp = tid >> 5;
    const int brow = blockIdx.y * BM, bcol = blockIdx.x * BN;
    const int wm = (warp >> 2) * 64, wn = (warp & 3) * 32;

    float acc[4][4][4];
#pragma unroll
    for (int i = 0; i < 4; i++)
#pragma unroll
        for (int j = 0; j < 4; j++)
#pragma unroll
            for (int q = 0; q < 4; q++) acc[i][j][q] = 0.f;

    const uint32_t smem_u32 = (uint32_t)__cvta_generic_to_shared(sm);

    float4 aReg[4], bReg[4];

    // ---- prologue: load + stash tile 0 ----
#pragma unroll
    for (int p = 0; p < 4; p++) {
        int idx = tid + p * 256;
        int r = idx >> 3, c4 = (idx & 7) << 2;
        aReg[p] = *(const float4*)&A[(size_t)(brow + r) * EMB + c4];
        int rb = idx >> 5, cb = (idx & 31) << 2;
        bReg[p] = *(const float4*)&B[(size_t)rb * EMB + bcol + cb];
    }
    {
        __nv_bfloat16* base = sm;   // stage 0
#pragma unroll
        for (int p = 0; p < 4; p++) {
            int idx = tid + p * 256;
            {
                int r = idx >> 3, c4 = (idx & 7) << 2;
                float v[4] = {aReg[p].x, aReg[p].y, aReg[p].z, aReg[p].w};
                __nv_bfloat16 h[4], l[4];
#pragma unroll
                for (int q = 0; q < 4; q++) split1(v[q], h[q], l[q]);
                uint2 uh; uh.x = pack_bf16(h[0], h[1]); uh.y = pack_bf16(h[2], h[3]);
                uint2 ul; ul.x = pack_bf16(l[0], l[1]); ul.y = pack_bf16(l[2], l[3]);
                *(uint2*)(base + OFF_AH + r * ASTR + c4) = uh;
                *(uint2*)(base + OFF_AL + r * ASTR + c4) = ul;
            }
            {
                int rb = idx >> 5, cb = (idx & 31) << 2;
                float v[4] = {bReg[p].x, bReg[p].y, bReg[p].z, bReg[p].w};
                __nv_bfloat16 h[4], l[4];
#pragma unroll
                for (int q = 0; q < 4; q++) split1(v[q], h[q], l[q]);
                uint2 uh; uh.x = pack_bf16(h[0], h[1]); uh.y = pack_bf16(h[2], h[3]);
                uint2 ul; ul.x = pack_bf16(l[0], l[1]); ul.y = pack_bf16(l[2], l[3]);
                *(uint2*)(base + OFF_BH + rb * BSTR + cb) = uh;
                *(uint2*)(base + OFF_BL + rb * BSTR + cb) = ul;
            }
        }
    }
    __syncthreads();

    // ---- main loop ----
    for (int it = 0; it < NIT; it++) {
        if (it + 1 < NIT) {
            int k0 = (it + 1) * BKK;
#pragma unroll
            for (int p = 0; p < 4; p++) {
                int idx = tid + p * 256;
                int r = idx >> 3, c4 = (idx & 7) << 2;
                aReg[p] = *(const float4*)&A[(size_t)(brow + r) * EMB + k0 + c4];
                int rb = idx >> 5, cb = (idx & 31) << 2;
                bReg[p] = *(const float4*)&B[(size_t)(k0 + rb) * EMB + bcol + cb];
            }
        }
        const int s = it & 1;
        const uint32_t sb = smem_u32 + (uint32_t)(s * STAGE_ELEMS * 2);

#pragma unroll
        for (int kc = 0; kc < 2; kc++) {
            uint32_t aH[4][4], aL[4][4], bH[4][2], bL[4][2];
            // A fragments: rows m0 + (lane&15), col kc*16 + (lane>>4)*8
            const int arow = wm + (lane & 15);
            const int acol = kc * 16 + (lane >> 4) * 8;
#pragma unroll
            for (int i = 0; i < 4; i++) {
                uint32_t off = (uint32_t)(((arow + i * 16) * ASTR + acol) * 2);
                ldsm4(aH[i][0], aH[i][1], aH[i][2], aH[i][3], sb + OFF_AH * 2 + off);
                ldsm4(aL[i][0], aL[i][1], aL[i][2], aL[i][3], sb + OFF_AL * 2 + off);
            }
            // B fragments: row k = kc*16 + (lane&15), col n = wn + j2*16 + (lane>>4)*8
            const int bk = kc * 16 + (lane & 15);
#pragma unroll
            for (int j2 = 0; j2 < 2; j2++) {
                int n = wn + j2 * 16 + (lane >> 4) * 8;
                uint32_t off = (uint32_t)((bk * BSTR + n) * 2);
                ldsm4t(bH[j2 * 2][0], bH[j2 * 2][1], bH[j2 * 2 + 1][0], bH[j2 * 2 + 1][1],
                       sb + OFF_BH * 2 + off);
                ldsm4t(bL[j2 * 2][0], bL[j2 * 2][1], bL[j2 * 2 + 1][0], bL[j2 * 2 + 1][1],
                       sb + OFF_BL * 2 + off);
            }
#pragma unroll
            for (int i = 0; i < 4; i++)
#pragma unroll
                for (int j = 0; j < 4; j++) {
                    mma_bf16(acc[i][j], aH[i], bH[j]);
                    mma_bf16(acc[i][j], aH[i], bL[j]);
                    mma_bf16(acc[i][j], aL[i], bH[j]);
                }
        }

        if (it + 1 < NIT) {
            __nv_bfloat16* base = sm + (size_t)((it + 1) & 1) * STAGE_ELEMS;
#pragma unroll
            for (int p = 0; p < 4; p++) {
                int idx = tid + p * 256;
                {
                    int r = idx >> 3, c4 = (idx & 7) << 2;
                    float v[4] = {aReg[p].x, aReg[p].y, aReg[p].z, aReg[p].w};
                    __nv_bfloat16 h[4], l[4];
#pragma unroll
                    for (int q = 0; q < 4; q++) split1(v[q], h[q], l[q]);
                    uint2 uh; uh.x = pack_bf16(h[0], h[1]); uh.y = pack_bf16(h[2], h[3]);
                    uint2 ul; ul.x = pack_bf16(l[0], l[1]); ul.y = pack_bf16(l[2], l[3]);
                    *(uint2*)(base + OFF_AH + r * ASTR + c4) = uh;
                    *(uint2*)(base + OFF_AL + r * ASTR + c4) = ul;
                }
                {
                    int rb = idx >> 5, cb = (idx & 31) << 2;
                    float v[4] = {bReg[p].x, bReg[p].y, bReg[p].z, bReg[p].w};
                    __nv_bfloat16 h[4], l[4];
#pragma unroll
                    for (int q = 0; q < 4; q++) split1(v[q], h[q], l[q]);
                    uint2 uh; uh.x = pack_bf16(h[0], h[1]); uh.y = pack_bf16(h[2], h[3]);
                    uint2 ul; ul.x = pack_bf16(l[0], l[1]); ul.y = pack_bf16(l[2], l[3]);
                    *(uint2*)(base + OFF_BH + rb * BSTR + cb) = uh;
                    *(uint2*)(base + OFF_BL + rb * BSTR + cb) = ul;
                }
            }
        }
        __syncthreads();
    }

    // ---- epilogue: bias + store ----
    const int g = lane >> 2, t = lane & 3;
#pragma unroll
    for (int i = 0; i < 4; i++) {
        int r0 = brow + wm + i * 16 + g;
#pragma unroll
        for (int j = 0; j < 4; j++) {
            int col = bcol + wn + j * 8 + 2 * t;
            float2 bb = *(const float2*)&bias[col];
            float2 v0 = {acc[i][j][0] + bb.x, acc[i][j][1] + bb.y};
            float2 v1 = {acc[i][j][2] + bb.x, acc[i][j][3] + bb.y};
            *(float2*)&C[(size_t)r0 * EMB + col] = v0;
            *(float2*)&C[(size_t)(r0 + 8) * EMB + col] = v1;
        }
    }
}

// ============================================================================
// Flash-style attention (unchanged from passing R2): one thread per query row.
// ============================================================================
__global__ __launch_bounds__(128) void attn_kernel(
    const float* __restrict__ Q, const float* __restrict__ K,
    const float* __restrict__ V, const int* __restrict__ mask,
    float* __restrict__ O)
{
    __shared__ float kS[64][64];
    __shared__ float vS[64][64];

    const int t = threadIdx.x;
    const int n = blockIdx.z;
    const int h = blockIdx.y;
    const int qrow = blockIdx.x * 128 + t;
    const size_t headoff = (size_t)h * DK;

    const float* Qp = Q + ((size_t)n * SEQ + qrow) * EMB + headoff;
    float q[DK];
#pragma unroll
    for (int d = 0; d < DK; d++) q[d] = Qp[d] * 0.125f;

    float o[DK];
#pragma unroll
    for (int d = 0; d < DK; d++) o[d] = 0.f;
    float m = -1e30f, l = 0.f;

    const int* mrow = mask + ((size_t)n * SEQ + qrow) * SEQ;
    const float* Kbase = K + ((size_t)n * SEQ) * EMB + headoff;
    const float* Vbase = V + ((size_t)n * SEQ) * EMB + headoff;

    for (int j = 0; j < SEQ / 64; j++) {
        const int kb = j * 64;
        __syncthreads();
#pragma unroll
        for (int i = 0; i < 8; i++) {
            int idx = t + i * 128;
            int r = idx >> 4;
            int c = (idx & 15) << 2;
            *(float4*)&kS[r][c] = *(const float4*)&Kbase[(size_t)(kb + r) * EMB + c];
            *(float4*)&vS[r][c] = *(const float4*)&Vbase[(size_t)(kb + r) * EMB + c];
        }
        __syncthreads();

        float s[64];
#pragma unroll
        for (int k = 0; k < 64; k++) {
            float acc = 0.f;
#pragma unroll
            for (int d = 0; d < DK; d++) acc += q[d] * kS[k][d];
            s[k] = acc;
        }

#pragma unroll
        for (int k = 0; k < 64; k += 4) {
            int4 mv = *(const int4*)&mrow[kb + k];
            if (mv.x) s[k + 0] = -1e9f;
            if (mv.y) s[k + 1] = -1e9f;
            if (mv.z) s[k + 2] = -1e9f;
            if (mv.w) s[k + 3] = -1e9f;
        }

        float tmax = s[0];
#pragma unroll
        for (int k = 1; k < 64; k++) tmax = fmaxf(tmax, s[k]);
        float m_new = fmaxf(m, tmax);
        float c = __expf(m - m_new);
        l *= c;
        float sum = 0.f;
#pragma unroll
        for (int k = 0; k < 64; k++) {
            float p = __expf(s[k] - m_new);
            s[k] = p;
            sum += p;
        }
        l += sum;
#pragma unroll
        for (int d = 0; d < DK; d++) o[d] *= c;

#pragma unroll
        for (int d = 0; d < DK; d++) {
            float acc = o[d];
#pragma unroll
            for (int k = 0; k < 64; k++) acc += s[k] * vS[k][d];
            o[d] = acc;
        }
        m = m_new;
    }

    const float inv = 1.f / l;
    float* Op = O + ((size_t)n * SEQ + qrow) * EMB + headoff;
#pragma unroll
    for (int d = 0; d < DK; d += 4) {
        float4 v;
        v.x = o[d + 0] * inv;
        v.y = o[d + 1] * inv;
        v.z = o[d + 2] * inv;
        v.w = o[d + 3] * inv;
        *(float4*)&Op[d] = v;
    }
}

// ============================================================================
// Launch
// ============================================================================
extern "C" void kernel_launch(void* const* d_in, const int* in_sizes, int n_in,
                              void* d_out, int out_size)
{
    const float* x  = (const float*)d_in[0];
    const int* mask = (const int*)d_in[1];
    const float* Wq = (const float*)d_in[2];
    const float* bq = (const float*)d_in[3];
    const float* Wk = (const float*)d_in[4];
    const float* bk = (const float*)d_in[5];
    const float* Wv = (const float*)d_in[6];
    const float* bv = (const float*)d_in[7];
    const float* Wo = (const float*)d_in[8];
    const float* bo = (const float*)d_in[9];
    float* out = (float*)d_out;

    float *Qp, *Kp, *Vp, *Op;
    cudaGetSymbolAddress((void**)&Qp, g_Q);
    cudaGetSymbolAddress((void**)&Kp, g_K);
    cudaGetSymbolAddress((void**)&Vp, g_V);
    cudaGetSymbolAddress((void**)&Op, g_O);

    cudaFuncSetAttribute(gemm_bf16x3_kernel,
                         cudaFuncAttributeMaxDynamicSharedMemorySize, GEMM_SMEM_BYTES);

    dim3 ggrid(EMB / BN, MROWS / BM);   // (8, 64)
    gemm_bf16x3_kernel<<<ggrid, 256, GEMM_SMEM_BYTES>>>(x, Wq, bq, Qp);
    gemm_bf16x3_kernel<<<ggrid, 256, GEMM_SMEM_BYTES>>>(x, Wk, bk, Kp);
    gemm_bf16x3_kernel<<<ggrid, 256, GEMM_SMEM_BYTES>>>(x, Wv, bv, Vp);

    dim3 agrid(SEQ / 128, NH, NB);      // (8, 16, 8)
    attn_kernel<<<agrid, 128>>>(Qp, Kp, Vp, mask, Op);

    gemm_bf16x3_kernel<<<ggrid, 256, GEMM_SMEM_BYTES>>>(Op, Wo, bo, out);
}